// round 3
// baseline (speedup 1.0000x reference)
#include <cuda_runtime.h>

#define BETA   0.9f
#define NT     32                 // time steps
#define TILE_Q 256                // pooled (q) positions per CTA
#define NTHR   512                // threads per CTA: (q, co-half)
#define NP     (2 * TILE_Q + 2)   // spk1 positions incl. halo = 514
#define PSTR   520                // padded row stride for spike bytes
#define XCNT   1030               // x window floats needed
#define XPAD   1032

// dynamic smem layout (bytes)
#define LUT_BYTES (3 * 256 * 4 * 8 * 4)      // 98304: lutR[3][256][4 copies][8 co]
#define SB_OFF    LUT_BYTES                   // spike bytes [NT][PSTR] = 16640
#define SX_OFF    (SB_OFF + NT * PSTR)        // sx floats (aliased by psum later)
#define SMEM_TOTAL (SX_OFF + XPAD * 4)        // 119072

// [b][tile][t][o] partial FC sums
__device__ float g_partial[256 * 8 * NT * 2];

__device__ __forceinline__ float4 add4(float4 a, float4 b) {
    return make_float4(a.x + b.x, a.y + b.y, a.z + b.z, a.w + b.w);
}
__device__ __forceinline__ float4 max4(float4 a, float4 b) {
    return make_float4(fmaxf(a.x, b.x), fmaxf(a.y, b.y),
                       fmaxf(a.z, b.z), fmaxf(a.w, b.w));
}

__global__ void dummy_k() {}

__global__ __launch_bounds__(NTHR) void snn_main(
    const float* __restrict__ x,     // [256,1,8192]
    const float* __restrict__ w1,    // [8,1,3]
    const float* __restrict__ b1,    // [8]
    const float* __restrict__ w2,    // [8,8,3]
    const float* __restrict__ b2,    // [8]
    const float* __restrict__ fcw,   // [2,16384]
    const float* __restrict__ th1p,
    const float* __restrict__ th2p)
{
    extern __shared__ __align__(16) unsigned char smem[];
    float*         lutR = reinterpret_cast<float*>(smem);           // [3][256][4][8]
    unsigned char* sb   = smem + SB_OFF;                            // [NT][PSTR]
    float*         sx   = reinterpret_cast<float*>(smem + SX_OFF);  // [XPAD]
    // psum[t][warp][o] aliases sx (sx dead after layer-1): 32*16*2*4 = 4096 B
    float (*psum)[16][2] = reinterpret_cast<float (*)[16][2]>(smem + SX_OFF);

    const int blk  = blockIdx.x;
    const int b    = blk >> 3;      // sample
    const int tile = blk & 7;       // L-tile (8 per sample)
    const int tid  = threadIdx.x;
    const int q0   = tile * TILE_Q;
    const float th1 = *th1p;
    const float th2 = *th2p;

    // ---- Build conv2 byte-LUTs, replicated 4x:
    // lutR[k][s][j][co] = sum_{ci in s} w2[co][ci][k]  (+ bias folded into k=1)
    for (int idx = tid; idx < 3 * 256; idx += NTHR) {
        const int k = idx >> 8;
        const int s = idx & 255;
        float acc[8];
        #pragma unroll
        for (int co = 0; co < 8; co++) acc[co] = (k == 1) ? b2[co] : 0.f;
        #pragma unroll
        for (int ci = 0; ci < 8; ci++) {
            if ((s >> ci) & 1) {
                #pragma unroll
                for (int co = 0; co < 8; co++)
                    acc[co] += w2[(co * 8 + ci) * 3 + k];
            }
        }
        float* row = lutR + idx * 32;   // 4 copies x 8 floats
        #pragma unroll
        for (int j = 0; j < 4; j++)
            #pragma unroll
            for (int co = 0; co < 8; co++)
                row[j * 8 + co] = acc[co];
    }

    // ---- Load the x window this tile needs (zero-padded at edges)
    const int xbase = 4 * q0 - 3;
    const float* xb = x + b * 8192;
    for (int i = tid; i < XCNT; i += NTHR) {
        const int xg = xbase + i;
        sx[i] = (xg >= 0 && xg < 8192) ? xb[xg] : 0.f;
    }
    __syncthreads();

    // ---- Layer 1: conv1 + maxpool2 + 32-step LIF -> spike bytes in SMEM
    for (int ll = tid; ll < NP; ll += NTHR) {
        const int lg = (2 * q0 - 1) + ll;   // global spk1 position
        if (lg < 0 || lg >= 4096) {
            for (int t = 0; t < NT; t++) sb[t * PSTR + ll] = 0;
            continue;
        }
        const float x0 = sx[2 * ll], x1 = sx[2 * ll + 1];
        const float x2 = sx[2 * ll + 2], x3 = sx[2 * ll + 3];
        float cur[8], m[8];
        #pragma unroll
        for (int c = 0; c < 8; c++) {
            const float wa = w1[3 * c], wb = w1[3 * c + 1], wc = w1[3 * c + 2];
            const float y0 = wa * x0 + wb * x1 + wc * x2;
            const float y1 = wa * x1 + wb * x2 + wc * x3;
            cur[c] = fmaxf(y0, y1) + b1[c];
            m[c] = 0.f;
        }
        bool sp[8];
        #pragma unroll
        for (int c = 0; c < 8; c++) sp[c] = false;
        for (int t = 0; t < NT; t++) {
            unsigned byte = 0;
            #pragma unroll
            for (int c = 0; c < 8; c++) {
                // reset uses carry-in mem > th == previous step's spike
                float mm = BETA * m[c] + cur[c];
                if (sp[c]) mm -= th1;
                m[c] = mm;
                sp[c] = mm > th1;
                if (sp[c]) byte |= (1u << c);
            }
            sb[t * PSTR + ll] = (unsigned char)byte;
        }
    }

    // ---- Thread role: q = tid>>1, half = tid&1, LUT copy j = q&3.
    // Within any 8-lane LDS phase, 16B slot = (2j+h)&7 = phase lane index
    // -> gathers are conflict-free regardless of the spike byte values.
    const int qloc = tid >> 1;
    const int h    = tid & 1;
    const int qg   = q0 + qloc;
    const int jcpy = qloc & 3;

    float fw0[4], fw1[4], m2[4];
    #pragma unroll
    for (int j = 0; j < 4; j++) {
        fw0[j] = fcw[(4 * h + j) * 2048 + qg];
        fw1[j] = fcw[16384 + (4 * h + j) * 2048 + qg];
        m2[j] = 0.f;
    }
    __syncthreads();

    const int lane = tid & 31, wrp = tid >> 5;
    const int p = 2 * qloc;   // local index of s_{2q-1} in sb row
    // per-thread base into lutR: copy jcpy, half h (in floats)
    const float* lutT = lutR + jcpy * 8 + 4 * h;

    // ---- Main time loop: conv2(LUT) + pool + LIF2 + FC partial
    #pragma unroll 1
    for (int t = 0; t < NT; t++) {
        const unsigned char* row = sb + t * PSTR;
        const unsigned s0 = row[p], s1 = row[p + 1];
        const unsigned s2 = row[p + 2], s3 = row[p + 3];

        const float4 A0 = *reinterpret_cast<const float4*>(lutT + (0 * 256 + s0) * 32);
        const float4 A1 = *reinterpret_cast<const float4*>(lutT + (1 * 256 + s1) * 32);
        const float4 A2 = *reinterpret_cast<const float4*>(lutT + (2 * 256 + s2) * 32);
        const float4 B0 = *reinterpret_cast<const float4*>(lutT + (0 * 256 + s1) * 32);
        const float4 B1 = *reinterpret_cast<const float4*>(lutT + (1 * 256 + s2) * 32);
        const float4 B2 = *reinterpret_cast<const float4*>(lutT + (2 * 256 + s3) * 32);

        const float4 y0 = add4(add4(A0, A1), A2);
        const float4 y1 = add4(add4(B0, B1), B2);
        const float4 cv = max4(y0, y1);
        float cur2[4] = {cv.x, cv.y, cv.z, cv.w};

        float p0 = 0.f, p1 = 0.f;
        #pragma unroll
        for (int j = 0; j < 4; j++) {
            float mm = m2[j];
            const bool r = mm > th2;        // reset from carry-in mem
            mm = BETA * mm + cur2[j];
            if (r) mm -= th2;
            m2[j] = mm;
            if (mm > th2) { p0 += fw0[j]; p1 += fw1[j]; }
        }
        #pragma unroll
        for (int off = 16; off > 0; off >>= 1) {
            p0 += __shfl_down_sync(0xffffffffu, p0, off);
            p1 += __shfl_down_sync(0xffffffffu, p1, off);
        }
        if (lane == 0) { psum[t][wrp][0] = p0; psum[t][wrp][1] = p1; }
    }
    __syncthreads();

    if (tid < 64) {
        const int t = tid >> 1, o = tid & 1;
        float s = psum[t][0][o];
        #pragma unroll
        for (int w = 1; w < 16; w++) s += psum[t][w][o];
        g_partial[((b * 8 + tile) * NT + t) * 2 + o] = s;
    }
}

__global__ __launch_bounds__(64) void snn_final(
    const float* __restrict__ fcb,
    const float* __restrict__ thop,
    float* __restrict__ out)
{
    __shared__ float sm[NT][2];
    const int b = blockIdx.x;
    const int tid = threadIdx.x;

    {
        const int t = tid >> 1, o = tid & 1;
        float s = 0.f;
        #pragma unroll
        for (int tile = 0; tile < 8; tile++)
            s += g_partial[((b * 8 + tile) * NT + t) * 2 + o];
        sm[t][o] = s;
    }
    __syncthreads();

    if (tid < 2) {
        const int o = tid;
        const float tho = *thop;
        const float fb = fcb[o];
        float m = 0.f;
        for (int t = 0; t < NT; t++) {
            const float c = sm[t][o] + fb;
            const bool r = m > tho;
            m = BETA * m + c;
            if (r) m -= tho;
            const int base = (t * 256 + b) * 2 + o;
            out[base] = (m > tho) ? 1.f : 0.f;    // spk_rec
            out[16384 + base] = m;                // mem_rec
        }
    }
}

extern "C" void kernel_launch(void* const* d_in, const int* in_sizes, int n_in,
                              void* d_out, int out_size)
{
    const float* x    = (const float*)d_in[0];
    const float* w1   = (const float*)d_in[1];
    const float* b1   = (const float*)d_in[2];
    const float* w2   = (const float*)d_in[3];
    const float* b2   = (const float*)d_in[4];
    const float* fcw  = (const float*)d_in[5];
    const float* fcb  = (const float*)d_in[6];
    const float* th1  = (const float*)d_in[7];
    const float* th2  = (const float*)d_in[8];
    const float* tho  = (const float*)d_in[9];
    float* out = (float*)d_out;

    cudaFuncSetAttribute(snn_main, cudaFuncAttributeMaxDynamicSharedMemorySize,
                         SMEM_TOTAL);

    // Launch order [dummy, main, final, dummy] so ncu's "-s 5 -c 1" capture
    // (launch index 5) lands on snn_main instead of snn_final.
    dummy_k<<<1, 32>>>();
    snn_main<<<256 * 8, NTHR, SMEM_TOTAL>>>(x, w1, b1, w2, b2, fcw, th1, th2);
    snn_final<<<256, 64>>>(fcb, tho, out);
    dummy_k<<<1, 32>>>();
}

// round 4
// speedup vs baseline: 1.0751x; 1.0751x over previous
#include <cuda_runtime.h>

#define BETA   0.9f
#define NT     32                 // time steps
#define TCH    8                  // time chunk
#define NCHUNK (NT / TCH)
#define TILE_Q 255                // pooled (q) positions per CTA
#define NTILE  9                  // ceil(2048/255)
#define NTHR   512
#define NP     512                // = 2*TILE_Q + 2 spk1 positions incl. halo
#define PSTR   520                // padded row stride for spike bytes
#define XCNT   1026               // x window floats needed
#define XPAD   1028

// dynamic smem layout (bytes)
#define LUT_BYTES (3 * 256 * 4 * 8 * 4)       // 98304: lutR[3][256][4 copies][8 co]
#define SB_OFF    LUT_BYTES                    // spike bytes [TCH][PSTR] = 4160
#define SX_OFF    (SB_OFF + TCH * PSTR)        // sx floats
#define PS_OFF    (SX_OFF + XPAD * 4)          // psum [NT][16][2] = 4096
#define SMEM_TOTAL (PS_OFF + NT * 16 * 2 * 4)  // 110672

// [b][tile][t][o] partial FC sums
__device__ float g_partial[256 * NTILE * NT * 2];

__device__ __forceinline__ float4 add4(float4 a, float4 b) {
    return make_float4(a.x + b.x, a.y + b.y, a.z + b.z, a.w + b.w);
}
__device__ __forceinline__ float4 max4(float4 a, float4 b) {
    return make_float4(fmaxf(a.x, b.x), fmaxf(a.y, b.y),
                       fmaxf(a.z, b.z), fmaxf(a.w, b.w));
}

__global__ void dummy_k() {}

__global__ __launch_bounds__(NTHR, 2) void snn_main(
    const float* __restrict__ x,     // [256,1,8192]
    const float* __restrict__ w1,    // [8,1,3]
    const float* __restrict__ b1,    // [8]
    const float* __restrict__ w2,    // [8,8,3]
    const float* __restrict__ b2,    // [8]
    const float* __restrict__ fcw,   // [2,16384]
    const float* __restrict__ th1p,
    const float* __restrict__ th2p)
{
    extern __shared__ __align__(16) unsigned char smem[];
    float*         lutR = reinterpret_cast<float*>(smem);           // [3][256][4][8]
    unsigned char* sb   = smem + SB_OFF;                            // [TCH][PSTR]
    float*         sx   = reinterpret_cast<float*>(smem + SX_OFF);  // [XPAD]
    float (*psum)[16][2] = reinterpret_cast<float (*)[16][2]>(smem + PS_OFF);

    const int blk  = blockIdx.x;
    const int b    = blk / NTILE;
    const int tile = blk - b * NTILE;
    const int tid  = threadIdx.x;
    const int q0   = tile * TILE_Q;
    const float th1 = *th1p;
    const float th2 = *th2p;

    // ---- Build conv2 byte-LUTs, replicated 4x (conflict-free gathers):
    // lutR[k][s][j][co] = sum_{ci in s} w2[co][ci][k]  (+ bias folded into k=1)
    for (int idx = tid; idx < 3 * 256; idx += NTHR) {
        const int k = idx >> 8;
        const int s = idx & 255;
        float acc[8];
        #pragma unroll
        for (int co = 0; co < 8; co++) acc[co] = (k == 1) ? b2[co] : 0.f;
        #pragma unroll
        for (int ci = 0; ci < 8; ci++) {
            if ((s >> ci) & 1) {
                #pragma unroll
                for (int co = 0; co < 8; co++)
                    acc[co] += w2[(co * 8 + ci) * 3 + k];
            }
        }
        float4* row = reinterpret_cast<float4*>(lutR + idx * 32);
        const float4 lo = make_float4(acc[0], acc[1], acc[2], acc[3]);
        const float4 hi = make_float4(acc[4], acc[5], acc[6], acc[7]);
        #pragma unroll
        for (int j = 0; j < 4; j++) { row[2 * j] = lo; row[2 * j + 1] = hi; }
    }

    // ---- Load the x window this tile needs (zero-padded at edges)
    const int xbase = 4 * q0 - 3;
    const float* xb = x + b * 8192;
    for (int i = tid; i < XCNT; i += NTHR) {
        const int xg = xbase + i;
        sx[i] = (xg >= 0 && xg < 8192) ? xb[xg] : 0.f;
    }
    __syncthreads();

    // ---- Layer-1 init: one spk1 position per thread, state in registers
    const int lg = (2 * q0 - 1) + tid;            // global spk1 position
    const bool pvalid = (lg >= 0 && lg < 4096);
    float cur[8], m[8];
    {
        const float x0 = sx[2 * tid],     x1 = sx[2 * tid + 1];
        const float x2 = sx[2 * tid + 2], x3 = sx[2 * tid + 3];
        #pragma unroll
        for (int c = 0; c < 8; c++) {
            const float wa = w1[3 * c], wb = w1[3 * c + 1], wc = w1[3 * c + 2];
            const float y0 = wa * x0 + wb * x1 + wc * x2;
            const float y1 = wa * x1 + wb * x2 + wc * x3;
            cur[c] = fmaxf(y0, y1) + b1[c];
            m[c] = 0.f;
        }
    }
    unsigned sp1 = 0;   // previous-step spike bits for layer 1

    // ---- Thread role for conv2/FC: q = tid>>1, h = tid&1 (owns co 4h..4h+3),
    // LUT copy j = q&3 -> 8-lane LDS phases are conflict-free for any data.
    const int qloc = tid >> 1;
    const int h    = tid & 1;
    const int qg   = q0 + qloc;
    const bool qvalid = (qloc < TILE_Q) && (qg < 2048);
    const float* lutT = lutR + (qloc & 3) * 8 + 4 * h;

    // FC weights: this thread accumulates output o=h over ALL 8 co of its q
    float fw[8], m2[4];
    #pragma unroll
    for (int co = 0; co < 8; co++)
        fw[co] = qvalid ? fcw[h * 16384 + co * 2048 + qg] : 0.f;
    #pragma unroll
    for (int j = 0; j < 4; j++) m2[j] = 0.f;

    const int lane = tid & 31, wrp = tid >> 5;
    const int p = 2 * qloc;

    // ==== Chunked time loop ====
    #pragma unroll 1
    for (int ch = 0; ch < NCHUNK; ch++) {
        // -- produce TCH rows of layer-1 spike bytes
        #pragma unroll
        for (int tt = 0; tt < TCH; tt++) {
            unsigned byte = 0;
            if (pvalid) {
                #pragma unroll
                for (int c = 0; c < 8; c++) {
                    float mm = BETA * m[c] + cur[c];
                    if ((sp1 >> c) & 1) mm -= th1;
                    m[c] = mm;
                    if (mm > th1) byte |= (1u << c);
                }
                sp1 = byte;
            }
            sb[tt * PSTR + tid] = (unsigned char)byte;
        }
        __syncthreads();

        // -- consume: conv2(LUT) + pool + LIF2 + FC partial
        #pragma unroll 1
        for (int tt = 0; tt < TCH; tt++) {
            const unsigned char* row = sb + tt * PSTR;
            const unsigned s0 = row[p], s1 = row[p + 1];
            const unsigned s2 = row[p + 2], s3 = row[p + 3];

            const float4 A0 = *reinterpret_cast<const float4*>(lutT + (0 * 256 + s0) * 32);
            const float4 A1 = *reinterpret_cast<const float4*>(lutT + (1 * 256 + s1) * 32);
            const float4 A2 = *reinterpret_cast<const float4*>(lutT + (2 * 256 + s2) * 32);
            const float4 B0 = *reinterpret_cast<const float4*>(lutT + (0 * 256 + s1) * 32);
            const float4 B1 = *reinterpret_cast<const float4*>(lutT + (1 * 256 + s2) * 32);
            const float4 B2 = *reinterpret_cast<const float4*>(lutT + (2 * 256 + s3) * 32);

            const float4 cv = max4(add4(add4(A0, A1), A2), add4(add4(B0, B1), B2));
            const float cur2[4] = {cv.x, cv.y, cv.z, cv.w};

            unsigned nib = 0;
            #pragma unroll
            for (int j = 0; j < 4; j++) {
                float mm = m2[j];
                const bool r = mm > th2;          // reset from carry-in mem
                mm = BETA * mm + cur2[j];
                if (r) mm -= th2;
                m2[j] = mm;
                if (mm > th2) nib |= (1u << j);
            }
            // full 8-co spike mask for this q: own half | partner half
            const unsigned own  = nib << (4 * h);
            const unsigned full = own | __shfl_xor_sync(0xffffffffu, own, 1);

            float pacc = 0.f;
            #pragma unroll
            for (int co = 0; co < 8; co++)
                if ((full >> co) & 1) pacc += fw[co];

            // xor-butterfly over dists 2..16: lanes split by parity (= o)
            #pragma unroll
            for (int off = 2; off <= 16; off <<= 1)
                pacc += __shfl_xor_sync(0xffffffffu, pacc, off);

            if (lane < 2) psum[ch * TCH + tt][wrp][lane] = pacc;
        }
        __syncthreads();
    }

    if (tid < 64) {
        const int t = tid >> 1, o = tid & 1;
        float s = psum[t][0][o];
        #pragma unroll
        for (int w = 1; w < 16; w++) s += psum[t][w][o];
        g_partial[((b * NTILE + tile) * NT + t) * 2 + o] = s;
    }
}

__global__ __launch_bounds__(64) void snn_final(
    const float* __restrict__ fcb,
    const float* __restrict__ thop,
    float* __restrict__ out)
{
    __shared__ float sm[NT][2];
    const int b = blockIdx.x;
    const int tid = threadIdx.x;

    {
        const int t = tid >> 1, o = tid & 1;
        float s = 0.f;
        #pragma unroll
        for (int tile = 0; tile < NTILE; tile++)
            s += g_partial[((b * NTILE + tile) * NT + t) * 2 + o];
        sm[t][o] = s;
    }
    __syncthreads();

    if (tid < 2) {
        const int o = tid;
        const float tho = *thop;
        const float fb = fcb[o];
        float mo = 0.f;
        for (int t = 0; t < NT; t++) {
            const float c = sm[t][o] + fb;
            const bool r = mo > tho;
            mo = BETA * mo + c;
            if (r) mo -= tho;
            const int base = (t * 256 + b) * 2 + o;
            out[base] = (mo > tho) ? 1.f : 0.f;   // spk_rec
            out[16384 + base] = mo;               // mem_rec
        }
    }
}

extern "C" void kernel_launch(void* const* d_in, const int* in_sizes, int n_in,
                              void* d_out, int out_size)
{
    const float* x    = (const float*)d_in[0];
    const float* w1   = (const float*)d_in[1];
    const float* b1   = (const float*)d_in[2];
    const float* w2   = (const float*)d_in[3];
    const float* b2   = (const float*)d_in[4];
    const float* fcw  = (const float*)d_in[5];
    const float* fcb  = (const float*)d_in[6];
    const float* th1  = (const float*)d_in[7];
    const float* th2  = (const float*)d_in[8];
    const float* tho  = (const float*)d_in[9];
    float* out = (float*)d_out;

    cudaFuncSetAttribute(snn_main, cudaFuncAttributeMaxDynamicSharedMemorySize,
                         SMEM_TOTAL);

    // 5-launch period [main, final, d, d, d] -> ncu "-s 5" (6th launch) = main
    snn_main<<<256 * NTILE, NTHR, SMEM_TOTAL>>>(x, w1, b1, w2, b2, fcw, th1, th2);
    snn_final<<<256, 64>>>(fcb, tho, out);
    dummy_k<<<1, 32>>>();
    dummy_k<<<1, 32>>>();
    dummy_k<<<1, 32>>>();
}